// round 16
// baseline (speedup 1.0000x reference)
#include <cuda_runtime.h>
#include <cuda_bf16.h>
#include <math.h>
#include <stdint.h>

// ---------------- problem constants ----------------
#define BATCH   32
#define SEQ     1000
#define DMODEL  256
#define PATCHSZ 160
#define NLAYERS 6
#define G3      768   // 3*DMODEL

// ---------------- scratch (device globals; no allocs allowed) ----------------
__device__ float g_x [BATCH * SEQ * DMODEL];   // residual stream x
__device__ float g_stats[BATCH * SEQ * 2];     // per-row LN (mu, rsigma)
__device__ float g_xp[BATCH * SEQ * G3];       // input projection per layer
__device__ float g_emb[BATCH * DMODEL];        // pooled embedding
__device__ float g_part[BATCH * 25 * DMODEL];  // final-LN partial sums

__device__ __forceinline__ float gelu_exact(float v) {
    return 0.5f * v * (1.0f + erff(v * 0.70710678118654752440f));
}
__device__ __forceinline__ float fsigmoid(float v) {
    return __fdividef(1.0f, 1.0f + __expf(-v));
}
__device__ __forceinline__ float ftanh(float v) {
    return 1.0f - __fdividef(2.0f, __expf(2.0f * v) + 1.0f);
}

// packed f32x2 helpers
__device__ __forceinline__ unsigned long long pk2(float lo, float hi) {
    unsigned long long r;
    asm("mov.b64 %0, {%1, %2};" : "=l"(r) : "f"(lo), "f"(hi));
    return r;
}
__device__ __forceinline__ void upk2(unsigned long long v, float& lo, float& hi) {
    asm("mov.b64 {%0, %1}, %2;" : "=f"(lo), "=f"(hi) : "l"(v));
}
__device__ __forceinline__ unsigned long long fma2(unsigned long long a,
                                                   unsigned long long b,
                                                   unsigned long long c) {
    unsigned long long r;
    asm("fma.rn.f32x2 %0, %1, %2, %3;" : "=l"(r) : "l"(a), "l"(b), "l"(c));
    return r;
}
__device__ __forceinline__ unsigned long long add2(unsigned long long a,
                                                   unsigned long long b) {
    unsigned long long r;
    asm("add.rn.f32x2 %0, %1, %2;" : "=l"(r) : "l"(a), "l"(b));
    return r;
}

// local mbarrier parity wait (acquire.cta — data arrives via async proxy tx)
__device__ __forceinline__ void mbar_wait(uint32_t mb, unsigned par) {
    unsigned done;
    asm volatile(
        "{\n\t.reg .pred p;\n\t"
        "mbarrier.try_wait.parity.acquire.cta.shared::cta.b64 p, [%1], %2;\n\t"
        "selp.b32 %0, 1, 0, p;\n\t}"
        : "=r"(done) : "r"(mb), "r"(par) : "memory");
    if (!done) {
        asm volatile(
            "{\n\t.reg .pred P1;\n\t"
            "WL%=:\n\t"
            "mbarrier.try_wait.parity.acquire.cta.shared::cta.b64 P1, [%0], %1, 0x989680;\n\t"
            "@P1 bra.uni WD%=;\n\t"
            "bra.uni WL%=;\n\t"
            "WD%=:\n\t}"
            :: "r"(mb), "r"(par) : "memory");
    }
}

// =====================================================================
// Kernel 1: patchify conv (k=stride=160) + exact GELU + pos emb -> g_x
// =====================================================================
__global__ __launch_bounds__(256) void k_conv(const float* __restrict__ wave,
                                              const float* __restrict__ cw,
                                              const float* __restrict__ pos) {
    __shared__ __align__(16) float sw[64 * PATCHSZ];   // 40 KB
    const int tid = threadIdx.x;
    const long base = (long)blockIdx.x * 64 * PATCHSZ;

    const float4* src = (const float4*)(wave + base);
    float4* dst = (float4*)sw;
#pragma unroll
    for (int i = 0; i < 10; i++) dst[tid + i * 256] = src[tid + i * 256];

    float creg[PATCHSZ];
#pragma unroll
    for (int p = 0; p < PATCHSZ; p++) creg[p] = cw[p * DMODEL + tid];
    __syncthreads();

    const int row0 = blockIdx.x * 64;
    for (int r = 0; r < 64; r++) {
        const float4* wv = (const float4*)(sw + r * PATCHSZ);
        float acc = 0.0f;
#pragma unroll
        for (int i = 0; i < PATCHSZ / 4; i++) {
            float4 v = wv[i];
            acc += v.x * creg[4 * i + 0];
            acc += v.y * creg[4 * i + 1];
            acc += v.z * creg[4 * i + 2];
            acc += v.w * creg[4 * i + 3];
        }
        const int row = row0 + r;
        const int s = row % SEQ;
        g_x[(long)row * DMODEL + tid] = gelu_exact(acc) + pos[s * DMODEL + tid];
    }
}

// =====================================================================
// Kernel 2: LN row stats (mu, rsigma) -> g_stats. one warp per row.
// grid 4000, block 256 (8 rows / CTA).
// =====================================================================
__global__ __launch_bounds__(256) void k_ln_stats() {
    const int wid = threadIdx.x >> 5, lane = threadIdx.x & 31;
    const long row = (long)blockIdx.x * 8 + wid;
    const float4* xr = (const float4*)(g_x + row * DMODEL);
    float4 v0 = xr[lane];
    float4 v1 = xr[lane + 32];
    float s1 = v0.x + v0.y + v0.z + v0.w + v1.x + v1.y + v1.z + v1.w;
    float s2 = v0.x * v0.x + v0.y * v0.y + v0.z * v0.z + v0.w * v0.w
             + v1.x * v1.x + v1.y * v1.y + v1.z * v1.z + v1.w * v1.w;
#pragma unroll
    for (int o = 16; o > 0; o >>= 1) {
        s1 += __shfl_xor_sync(0xffffffffu, s1, o);
        s2 += __shfl_xor_sync(0xffffffffu, s2, o);
    }
    if (lane == 0) {
        const float mu  = s1 * (1.0f / 256.0f);
        const float var = s2 * (1.0f / 256.0f) - mu * mu;
        float2 st;
        st.x = mu;
        st.y = rsqrtf(var + 1e-5f);
        *(float2*)(g_stats + row * 2) = st;
    }
}

// =====================================================================
// Kernel 3: xp = LN(g_x)[32000,256] @ W_ih^T[256,768] + b_ih -> g_xp
// PERSISTENT grid (296 CTAs) over 1500 tiles of 128x128 — kills the
// 5.07-wave tail quantization. tile -> (bx=tile/6, by=tile%6) so 6
// concurrent CTAs share each A row-block in L2. LN fused into A load.
// K-chunk 32, 8x8 microtile, FFMA2 inner loop.
// =====================================================================
#define XP_TILES_X 250
#define XP_TILES   (XP_TILES_X * 6)

__global__ __launch_bounds__(256, 2) void k_gemm_xp(const float* __restrict__ W,
                                                    const float* __restrict__ bias,
                                                    const float* __restrict__ ln_sc,
                                                    const float* __restrict__ ln_bi) {
    __shared__ __align__(16) float As[32][132];   // [k][row] padded
    __shared__ __align__(16) float Bs[32][132];   // [k][col] padded
    __shared__ __align__(16) float sN[DMODEL];
    __shared__ __align__(16) float bN[DMODEL];
    const int tid = threadIdx.x;
    const int tx = tid & 15, ty = tid >> 4;

    sN[tid] = ln_sc[tid];
    bN[tid] = ln_bi[tid];
    __syncthreads();

    for (int tile = blockIdx.x; tile < XP_TILES; tile += gridDim.x) {
        const int row0 = (tile / 6) * 128;
        const int col0 = (tile % 6) * 128;

        unsigned long long acc2[4][8];   // [rowpair][col]
#pragma unroll
        for (int i = 0; i < 4; i++)
#pragma unroll
            for (int j = 0; j < 8; j++) acc2[i][j] = 0ull;

        for (int k0 = 0; k0 < DMODEL; k0 += 32) {
#pragma unroll
            for (int it = 0; it < 4; it++) {          // A tile: LN applied on load
                int m = tid + it * 256;
                int r = m >> 3, kq = (m & 7) * 4;
                const long row = row0 + r;
                float4 v = *(const float4*)(g_x + row * DMODEL + k0 + kq);
                float2 st = *(const float2*)(g_stats + row * 2);
                float4 s4 = *(const float4*)&sN[k0 + kq];
                float4 b4 = *(const float4*)&bN[k0 + kq];
                v.x = (v.x - st.x) * st.y * s4.x + b4.x;
                v.y = (v.y - st.x) * st.y * s4.y + b4.y;
                v.z = (v.z - st.x) * st.y * s4.z + b4.z;
                v.w = (v.w - st.x) * st.y * s4.w + b4.w;
                As[kq + 0][r] = v.x; As[kq + 1][r] = v.y;
                As[kq + 2][r] = v.z; As[kq + 3][r] = v.w;
            }
#pragma unroll
            for (int it = 0; it < 4; it++) {          // B tile (transposed store)
                int m = tid + it * 256;
                int cc = m >> 3, kq = (m & 7) * 4;
                float4 v = *(const float4*)(W + (long)(col0 + cc) * DMODEL + k0 + kq);
                Bs[kq + 0][cc] = v.x; Bs[kq + 1][cc] = v.y;
                Bs[kq + 2][cc] = v.z; Bs[kq + 3][cc] = v.w;
            }
            __syncthreads();
#pragma unroll
            for (int kk = 0; kk < 32; kk++) {
                // a: rows ty*8..ty*8+7 as 4 packed row-pairs
                ulonglong2 qa0 = *(const ulonglong2*)&As[kk][ty * 8];
                ulonglong2 qa1 = *(const ulonglong2*)&As[kk][ty * 8 + 4];
                unsigned long long ap0 = qa0.x, ap1 = qa0.y, ap2 = qa1.x, ap3 = qa1.y;
                // b: 8 cols, splat each
                float4 bv0 = *(const float4*)&Bs[kk][tx * 8];
                float4 bv1 = *(const float4*)&Bs[kk][tx * 8 + 4];
                unsigned long long bs[8];
                bs[0] = pk2(bv0.x, bv0.x); bs[1] = pk2(bv0.y, bv0.y);
                bs[2] = pk2(bv0.z, bv0.z); bs[3] = pk2(bv0.w, bv0.w);
                bs[4] = pk2(bv1.x, bv1.x); bs[5] = pk2(bv1.y, bv1.y);
                bs[6] = pk2(bv1.z, bv1.z); bs[7] = pk2(bv1.w, bv1.w);
#pragma unroll
                for (int j = 0; j < 8; j++) {
                    acc2[0][j] = fma2(ap0, bs[j], acc2[0][j]);
                    acc2[1][j] = fma2(ap1, bs[j], acc2[1][j]);
                    acc2[2][j] = fma2(ap2, bs[j], acc2[2][j]);
                    acc2[3][j] = fma2(ap3, bs[j], acc2[3][j]);
                }
            }
            __syncthreads();
        }
        // epilogue: rowpair rp -> rows ty*8+2rp (lo), +1 (hi); regs only,
        // so next tile's smem stores are safe after the k-loop's last sync.
        const int col = col0 + tx * 8;
        float4 bb0 = *(const float4*)(bias + col);
        float4 bb1 = *(const float4*)(bias + col + 4);
#pragma unroll
        for (int rp = 0; rp < 4; rp++) {
            float lo[8], hi[8];
#pragma unroll
            for (int j = 0; j < 8; j++) upk2(acc2[rp][j], lo[j], hi[j]);
            const long rlo = row0 + ty * 8 + 2 * rp;
            float4 u0, u1, v0, v1;
            u0.x = lo[0] + bb0.x; u0.y = lo[1] + bb0.y; u0.z = lo[2] + bb0.z; u0.w = lo[3] + bb0.w;
            u1.x = lo[4] + bb1.x; u1.y = lo[5] + bb1.y; u1.z = lo[6] + bb1.z; u1.w = lo[7] + bb1.w;
            v0.x = hi[0] + bb0.x; v0.y = hi[1] + bb0.y; v0.z = hi[2] + bb0.z; v0.w = hi[3] + bb0.w;
            v1.x = hi[4] + bb1.x; v1.y = hi[5] + bb1.y; v1.z = hi[6] + bb1.z; v1.w = hi[7] + bb1.w;
            *(float4*)(g_xp + rlo * G3 + col)           = u0;
            *(float4*)(g_xp + rlo * G3 + col + 4)       = u1;
            *(float4*)(g_xp + (rlo + 1) * G3 + col)     = v0;
            *(float4*)(g_xp + (rlo + 1) * G3 + col + 4) = v1;
        }
    }
}

// =====================================================================
// Kernel 4: GRU recurrence (R11 protocol). cluster(4) per batch,
// grid (4,32), block 384. Register-resident weights, dual FFMA2 chains.
// h TRIPLE-buffered; per-step sync via st.async complete_tx.
// Reduce path: NO shfl — both kh halves STS to interleaved s_part
// (even/odd banks, conflict-free); gate threads read LDS64 pairs.
// =====================================================================
__global__ void __cluster_dims__(4, 1, 1) __launch_bounds__(384, 1)
k_gru(const float* __restrict__ whh, const float* __restrict__ bhh) {
    __shared__ __align__(16) float h_buf[3][DMODEL];
    __shared__ __align__(16) float s_part[384];   // [o*2 + kh]
    __shared__ __align__(8) unsigned long long s_bar[3];

    const int c   = blockIdx.x;          // cluster rank 0..3
    const int b   = blockIdx.y;
    const int tid = threadIdx.x;
    const int w   = tid >> 5, l = tid & 31;
    const int o   = w * 16 + (l & 15);   // 0..191: CTA-local output index
    const int kh  = l >> 4;              // k half: 0 -> k[0,128), 1 -> k[128,256)
    const int gg  = o >> 6, dd = o & 63;
    const int R   = gg * DMODEL + c * 64 + dd;   // gate row in [0,768)

    // weight slice: 128 floats = 64 f32x2 pairs in registers
    unsigned long long wreg[64];
    {
        const ulonglong2* wp = (const ulonglong2*)(whh + (long)R * DMODEL + kh * 128);
#pragma unroll
        for (int i = 0; i < 32; i++) { ulonglong2 t2 = wp[i]; wreg[2*i] = t2.x; wreg[2*i+1] = t2.y; }
    }
    const float breg = (kh == 0) ? bhh[R] : 0.0f;

    // init h buffers + mbarriers (count=1: the local expect_tx arrive)
    for (int i = tid; i < 3 * DMODEL; i += 384) ((float*)h_buf)[i] = 0.0f;
    if (tid == 0) {
#pragma unroll
        for (int mm = 0; mm < 3; mm++) {
            uint32_t ba = (uint32_t)__cvta_generic_to_shared(&s_bar[mm]);
            asm volatile("mbarrier.init.shared.b64 [%0], %1;" :: "r"(ba), "r"(1u) : "memory");
        }
    }
    __syncthreads();
    // bars + zeroed buffers visible cluster-wide before any st.async
    asm volatile("barrier.cluster.arrive.aligned;\n\tbarrier.cluster.wait.aligned;" ::: "memory");

    const uint32_t bar_loc = (uint32_t)__cvta_generic_to_shared(&s_bar[0]);
    const uint32_t h_loc   = (uint32_t)__cvta_generic_to_shared(&h_buf[0][c * 64 + (tid & 63)]);

    const float* xpb = g_xp + (long)b * SEQ * G3;
    float* xb = g_x + (long)b * SEQ * DMODEL;
    const int d = c * 64 + tid;          // gate threads: tid < 64

    float pxr = 0.f, pxz = 0.f, pxn = 0.f, pxv = 0.f;
    float hold = 0.0f;
    if (tid < 64) {
        pxr = xpb[d]; pxz = xpb[256 + d]; pxn = xpb[512 + d];
        pxv = xb[c * 64 + tid];
    }

    unsigned ph[3] = {0u, 0u, 0u};       // const-indexed after unroll -> regs

    // steps 0..998 unrolled by 3 (m compile-time); tail step 999 after.
    for (int tb = 0; tb < SEQ - 1; tb += 3) {
#pragma unroll
        for (int sub = 0; sub < 3; sub++) {
            const int t = tb + sub;
            const int m = sub;
            const int q = (sub + 1) % 3;

            // post expect_tx for next buffer early (1024 B = 4 CTA x 64 x 4B)
            if (tid == 0) {
                asm volatile("mbarrier.arrive.expect_tx.shared.b64 _, [%0], %1;"
                             :: "r"(bar_loc + q * 8), "r"(1024u) : "memory");
            }
            if (t) { mbar_wait(bar_loc + m * 8, ph[m]); ph[m] ^= 1u; }

            // ---- matvec: 64 packed FFMA2 in two independent chains ----
            unsigned long long acc2  = pk2(breg, 0.0f);
            unsigned long long acc2b = pk2(0.0f, 0.0f);
            const ulonglong2* hv = (const ulonglong2*)&h_buf[m][kh * 128];
#pragma unroll
            for (int i = 0; i < 32; i++) {
                ulonglong2 h2 = hv[i];
                acc2  = fma2(wreg[2 * i],     h2.x, acc2);
                acc2b = fma2(wreg[2 * i + 1], h2.y, acc2b);
            }
            acc2 = add2(acc2, acc2b);
            float alo, ahi;
            upk2(acc2, alo, ahi);
            s_part[o * 2 + kh] = alo + ahi;   // even/odd banks: conflict-free
            __syncthreads();

            if (tid < 64) {
                float2 p0 = *(const float2*)&s_part[tid * 2];
                float2 p1 = *(const float2*)&s_part[(64 + tid) * 2];
                float2 p2 = *(const float2*)&s_part[(128 + tid) * 2];
                const float hr = p0.x + p0.y;
                const float hz = p1.x + p1.y;
                const float hn = p2.x + p2.y;
                const float rr = fsigmoid(pxr + hr);
                const float zz = fsigmoid(pxz + hz);
                const float nn = ftanh(pxn + rr * hn);
                const float hnew = nn + zz * (hold - nn);
                hold = hnew;

                // broadcast h to buf q of all 4 CTAs; stores carry the signal
                const uint32_t dst = h_loc + q * (DMODEL * 4);
                const uint32_t bq  = bar_loc + q * 8;
#pragma unroll
                for (int r = 0; r < 4; r++) {
                    uint32_t ra, rb;
                    asm("mapa.shared::cluster.u32 %0, %1, %2;" : "=r"(ra) : "r"(dst), "r"(r));
                    asm("mapa.shared::cluster.u32 %0, %1, %2;" : "=r"(rb) : "r"(bq),  "r"(r));
                    asm volatile(
                        "st.async.shared::cluster.mbarrier::complete_tx::bytes.f32 [%0], %1, [%2];"
                        :: "r"(ra), "f"(hnew), "r"(rb) : "memory");
                }
                // residual write + next-step prefetch (latency hidden)
                xb[(long)t * DMODEL + c * 64 + tid] = pxv + hnew;
                const float* xpt = xpb + (long)(t + 1) * G3;
                pxr = xpt[d]; pxz = xpt[256 + d]; pxn = xpt[512 + d];
                pxv = xb[(long)(t + 1) * DMODEL + c * 64 + tid];
            }
        }
    }
    // ---- tail step t = SEQ-1 (m = 0): no broadcast, residual only ----
    {
        const int t = SEQ - 1;
        mbar_wait(bar_loc + 0, ph[0]);
        unsigned long long acc2  = pk2(breg, 0.0f);
        unsigned long long acc2b = pk2(0.0f, 0.0f);
        const ulonglong2* hv = (const ulonglong2*)&h_buf[0][kh * 128];
#pragma unroll
        for (int i = 0; i < 32; i++) {
            ulonglong2 h2 = hv[i];
            acc2  = fma2(wreg[2 * i],     h2.x, acc2);
            acc2b = fma2(wreg[2 * i + 1], h2.y, acc2b);
        }
        acc2 = add2(acc2, acc2b);
        float alo, ahi;
        upk2(acc2, alo, ahi);
        s_part[o * 2 + kh] = alo + ahi;
        __syncthreads();
        if (tid < 64) {
            float2 p0 = *(const float2*)&s_part[tid * 2];
            float2 p1 = *(const float2*)&s_part[(64 + tid) * 2];
            float2 p2 = *(const float2*)&s_part[(128 + tid) * 2];
            const float hr = p0.x + p0.y;
            const float hz = p1.x + p1.y;
            const float hn = p2.x + p2.y;
            const float rr = fsigmoid(pxr + hr);
            const float zz = fsigmoid(pxz + hz);
            const float nn = ftanh(pxn + rr * hn);
            const float hnew = nn + zz * (hold - nn);
            xb[(long)t * DMODEL + c * 64 + tid] = pxv + hnew;
        }
    }
    // symmetric exit (no DSMEM traffic can target an exited CTA)
    asm volatile("barrier.cluster.arrive.aligned;\n\tbarrier.cluster.wait.aligned;" ::: "memory");
}

// =====================================================================
// Kernel 5a: final LN partials. grid (25 chunks, 32 batch), block 256.
// =====================================================================
__global__ __launch_bounds__(256) void k_final_part() {
    const int ch = blockIdx.x, b = blockIdx.y;
    const int wid = threadIdx.x >> 5, lane = threadIdx.x & 31;
    const float* xb = g_x + (long)b * SEQ * DMODEL;

    float a0[4] = {0, 0, 0, 0}, a1[4] = {0, 0, 0, 0};
    for (int i = 0; i < 5; i++) {
        const int t = ch * 40 + i * 8 + wid;
        const float4* xr = (const float4*)(xb + (long)t * DMODEL);
        float4 v0 = xr[lane];
        float4 v1 = xr[lane + 32];
        float s1 = v0.x + v0.y + v0.z + v0.w + v1.x + v1.y + v1.z + v1.w;
        float s2 = v0.x * v0.x + v0.y * v0.y + v0.z * v0.z + v0.w * v0.w
                 + v1.x * v1.x + v1.y * v1.y + v1.z * v1.z + v1.w * v1.w;
#pragma unroll
        for (int o = 16; o > 0; o >>= 1) {
            s1 += __shfl_xor_sync(0xffffffffu, s1, o);
            s2 += __shfl_xor_sync(0xffffffffu, s2, o);
        }
        const float mu  = s1 * (1.0f / 256.0f);
        const float var = s2 * (1.0f / 256.0f) - mu * mu;
        const float inv = rsqrtf(var + 1e-5f);
        a0[0] += (v0.x - mu) * inv; a0[1] += (v0.y - mu) * inv;
        a0[2] += (v0.z - mu) * inv; a0[3] += (v0.w - mu) * inv;
        a1[0] += (v1.x - mu) * inv; a1[1] += (v1.y - mu) * inv;
        a1[2] += (v1.z - mu) * inv; a1[3] += (v1.w - mu) * inv;
    }
    __shared__ float red[8][DMODEL];
    float* rw = red[wid];
    *(float4*)&rw[lane * 4]       = *(float4*)a0;
    *(float4*)&rw[128 + lane * 4] = *(float4*)a1;
    __syncthreads();
    const int tid = threadIdx.x;
    if (tid < 64) {
        const int dbase = tid * 4;
        float4 s = make_float4(0, 0, 0, 0);
#pragma unroll
        for (int ww = 0; ww < 8; ww++) {
            float4 v = *(float4*)&red[ww][dbase];
            s.x += v.x; s.y += v.y; s.z += v.z; s.w += v.w;
        }
        *(float4*)&g_part[((long)b * 25 + ch) * DMODEL + dbase] = s;
    }
}

// =====================================================================
// Kernel 5b: deterministic reduce of 25 partials + scale/bias + /SEQ.
// =====================================================================
__global__ __launch_bounds__(256) void k_final_sum(const float* __restrict__ sc,
                                                   const float* __restrict__ bi) {
    const int b = blockIdx.x, tid = threadIdx.x;
    float s = 0.0f;
#pragma unroll 5
    for (int ch = 0; ch < 25; ch++) s += g_part[((long)b * 25 + ch) * DMODEL + tid];
    g_emb[b * DMODEL + tid] = s * (1.0f / (float)SEQ) * sc[tid] + bi[tid];
}

// =====================================================================
// Kernel 6: classification head. grid 32, block 128.
// =====================================================================
__global__ __launch_bounds__(128) void k_head(const float* __restrict__ w1,
                                              const float* __restrict__ b1,
                                              const float* __restrict__ w2,
                                              const float* __restrict__ b2,
                                              float* __restrict__ out) {
    const int b = blockIdx.x, tid = threadIdx.x;
    __shared__ float es[DMODEL];
    __shared__ float h1s[128];
    es[tid]       = g_emb[b * DMODEL + tid];
    es[tid + 128] = g_emb[b * DMODEL + tid + 128];
    __syncthreads();
    float a = b1[tid];
#pragma unroll 8
    for (int dmi = 0; dmi < DMODEL; dmi++) a += es[dmi] * w1[dmi * 128 + tid];
    h1s[tid] = gelu_exact(a);
    __syncthreads();
    if (tid < 8) {
        float o = b2[tid];
#pragma unroll 8
        for (int j = 0; j < 128; j++) o += h1s[j] * w2[j * 8 + tid];
        out[b * 8 + tid] = o;
    }
}

// =====================================================================
// launch
// =====================================================================
extern "C" void kernel_launch(void* const* d_in, const int* in_sizes, int n_in,
                              void* d_out, int out_size) {
    const float* waveform = (const float*)d_in[0];
    const float* conv_w   = (const float*)d_in[1];
    const float* pos_emb  = (const float*)d_in[2];
    const float* ln_scale = (const float*)d_in[3];
    const float* ln_bias  = (const float*)d_in[4];
    const float* w_ih     = (const float*)d_in[5];
    const float* w_hh     = (const float*)d_in[6];
    const float* b_ih     = (const float*)d_in[7];
    const float* b_hh     = (const float*)d_in[8];
    const float* fnorm_s  = (const float*)d_in[9];
    const float* fnorm_b  = (const float*)d_in[10];
    const float* head_w1  = (const float*)d_in[11];
    const float* head_b1  = (const float*)d_in[12];
    const float* head_w2  = (const float*)d_in[13];
    const float* head_b2  = (const float*)d_in[14];
    float* out = (float*)d_out;

    k_conv<<<500, 256>>>(waveform, conv_w, pos_emb);

    for (int lyr = 0; lyr < NLAYERS; lyr++) {
        k_ln_stats<<<4000, 256>>>();
        k_gemm_xp<<<296, 256>>>(w_ih + (long)lyr * G3 * DMODEL, b_ih + lyr * G3,
                                ln_scale + lyr * DMODEL, ln_bias + lyr * DMODEL);
        dim3 gr(4, BATCH);
        k_gru<<<gr, 384>>>(w_hh + (long)lyr * G3 * DMODEL, b_hh + lyr * G3);
    }

    dim3 gf(25, BATCH);
    k_final_part<<<gf, 256>>>();
    k_final_sum<<<BATCH, 256>>>(fnorm_s, fnorm_b);
    k_head<<<BATCH, 128>>>(head_w1, head_b1, head_w2, head_b2, out);
}

// round 17
// speedup vs baseline: 1.0345x; 1.0345x over previous
#include <cuda_runtime.h>
#include <cuda_bf16.h>
#include <math.h>
#include <stdint.h>

// ---------------- problem constants ----------------
#define BATCH   32
#define SEQ     1000
#define DMODEL  256
#define PATCHSZ 160
#define NLAYERS 6
#define G3      768   // 3*DMODEL

// ---------------- scratch (device globals; no allocs allowed) ----------------
__device__ float g_x [BATCH * SEQ * DMODEL];   // residual stream x
__device__ float g_stats[BATCH * SEQ * 2];     // per-row LN (mu, rsigma)
__device__ float g_xp[BATCH * SEQ * G3];       // input projection per layer
__device__ float g_emb[BATCH * DMODEL];        // pooled embedding
__device__ float g_part[BATCH * 25 * DMODEL];  // final-LN partial sums

__device__ __forceinline__ float gelu_exact(float v) {
    return 0.5f * v * (1.0f + erff(v * 0.70710678118654752440f));
}
__device__ __forceinline__ float fsigmoid(float v) {
    return __fdividef(1.0f, 1.0f + __expf(-v));
}
__device__ __forceinline__ float ftanh(float v) {
    return 1.0f - __fdividef(2.0f, __expf(2.0f * v) + 1.0f);
}

// packed f32x2 helpers
__device__ __forceinline__ unsigned long long pk2(float lo, float hi) {
    unsigned long long r;
    asm("mov.b64 %0, {%1, %2};" : "=l"(r) : "f"(lo), "f"(hi));
    return r;
}
__device__ __forceinline__ void upk2(unsigned long long v, float& lo, float& hi) {
    asm("mov.b64 {%0, %1}, %2;" : "=f"(lo), "=f"(hi) : "l"(v));
}
__device__ __forceinline__ unsigned long long fma2(unsigned long long a,
                                                   unsigned long long b,
                                                   unsigned long long c) {
    unsigned long long r;
    asm("fma.rn.f32x2 %0, %1, %2, %3;" : "=l"(r) : "l"(a), "l"(b), "l"(c));
    return r;
}
__device__ __forceinline__ unsigned long long add2(unsigned long long a,
                                                   unsigned long long b) {
    unsigned long long r;
    asm("add.rn.f32x2 %0, %1, %2;" : "=l"(r) : "l"(a), "l"(b));
    return r;
}

// local mbarrier parity wait (acquire.cta — data arrives via async proxy tx)
__device__ __forceinline__ void mbar_wait(uint32_t mb, unsigned par) {
    unsigned done;
    asm volatile(
        "{\n\t.reg .pred p;\n\t"
        "mbarrier.try_wait.parity.acquire.cta.shared::cta.b64 p, [%1], %2;\n\t"
        "selp.b32 %0, 1, 0, p;\n\t}"
        : "=r"(done) : "r"(mb), "r"(par) : "memory");
    if (!done) {
        asm volatile(
            "{\n\t.reg .pred P1;\n\t"
            "WL%=:\n\t"
            "mbarrier.try_wait.parity.acquire.cta.shared::cta.b64 P1, [%0], %1, 0x989680;\n\t"
            "@P1 bra.uni WD%=;\n\t"
            "bra.uni WL%=;\n\t"
            "WD%=:\n\t}"
            :: "r"(mb), "r"(par) : "memory");
    }
}

// =====================================================================
// Kernel 1: patchify conv (k=stride=160) + exact GELU + pos emb -> g_x
// =====================================================================
__global__ __launch_bounds__(256) void k_conv(const float* __restrict__ wave,
                                              const float* __restrict__ cw,
                                              const float* __restrict__ pos) {
    __shared__ __align__(16) float sw[64 * PATCHSZ];   // 40 KB
    const int tid = threadIdx.x;
    const long base = (long)blockIdx.x * 64 * PATCHSZ;

    const float4* src = (const float4*)(wave + base);
    float4* dst = (float4*)sw;
#pragma unroll
    for (int i = 0; i < 10; i++) dst[tid + i * 256] = src[tid + i * 256];

    float creg[PATCHSZ];
#pragma unroll
    for (int p = 0; p < PATCHSZ; p++) creg[p] = cw[p * DMODEL + tid];
    __syncthreads();

    const int row0 = blockIdx.x * 64;
    for (int r = 0; r < 64; r++) {
        const float4* wv = (const float4*)(sw + r * PATCHSZ);
        float acc = 0.0f;
#pragma unroll
        for (int i = 0; i < PATCHSZ / 4; i++) {
            float4 v = wv[i];
            acc += v.x * creg[4 * i + 0];
            acc += v.y * creg[4 * i + 1];
            acc += v.z * creg[4 * i + 2];
            acc += v.w * creg[4 * i + 3];
        }
        const int row = row0 + r;
        const int s = row % SEQ;
        g_x[(long)row * DMODEL + tid] = gelu_exact(acc) + pos[s * DMODEL + tid];
    }
}

// =====================================================================
// Kernel 2: LN row stats (mu, rsigma) -> g_stats. one warp per row.
// grid 4000, block 256 (8 rows / CTA).
// =====================================================================
__global__ __launch_bounds__(256) void k_ln_stats() {
    const int wid = threadIdx.x >> 5, lane = threadIdx.x & 31;
    const long row = (long)blockIdx.x * 8 + wid;
    const float4* xr = (const float4*)(g_x + row * DMODEL);
    float4 v0 = xr[lane];
    float4 v1 = xr[lane + 32];
    float s1 = v0.x + v0.y + v0.z + v0.w + v1.x + v1.y + v1.z + v1.w;
    float s2 = v0.x * v0.x + v0.y * v0.y + v0.z * v0.z + v0.w * v0.w
             + v1.x * v1.x + v1.y * v1.y + v1.z * v1.z + v1.w * v1.w;
#pragma unroll
    for (int o = 16; o > 0; o >>= 1) {
        s1 += __shfl_xor_sync(0xffffffffu, s1, o);
        s2 += __shfl_xor_sync(0xffffffffu, s2, o);
    }
    if (lane == 0) {
        const float mu  = s1 * (1.0f / 256.0f);
        const float var = s2 * (1.0f / 256.0f) - mu * mu;
        float2 st;
        st.x = mu;
        st.y = rsqrtf(var + 1e-5f);
        *(float2*)(g_stats + row * 2) = st;
    }
}

// =====================================================================
// Kernel 3: xp = LN(g_x)[32000,256] @ W_ih^T[256,768] + b_ih -> g_xp
// NON-persistent grid (250,6) — hardware CTA scheduler load-balances the
// 5.07-wave remainder better than static persistence (R16 lesson).
// LN fused into A load; k-major tiles; FFMA2 inner loop (4 LDS128 +
// 8 MOV + 32 FFMA2 per kk).
// =====================================================================
__global__ __launch_bounds__(256, 2) void k_gemm_xp(const float* __restrict__ W,
                                                    const float* __restrict__ bias,
                                                    const float* __restrict__ ln_sc,
                                                    const float* __restrict__ ln_bi) {
    __shared__ __align__(16) float As[32][132];   // [k][row] padded
    __shared__ __align__(16) float Bs[32][132];   // [k][col] padded
    __shared__ __align__(16) float sN[DMODEL];
    __shared__ __align__(16) float bN[DMODEL];
    const int tid = threadIdx.x;
    const int tx = tid & 15, ty = tid >> 4;
    const int row0 = blockIdx.x * 128, col0 = blockIdx.y * 128;

    sN[tid] = ln_sc[tid];
    bN[tid] = ln_bi[tid];
    __syncthreads();

    unsigned long long acc2[4][8];   // [rowpair][col]
#pragma unroll
    for (int i = 0; i < 4; i++)
#pragma unroll
        for (int j = 0; j < 8; j++) acc2[i][j] = 0ull;

    for (int k0 = 0; k0 < DMODEL; k0 += 32) {
#pragma unroll
        for (int it = 0; it < 4; it++) {          // A tile: LN applied on load
            int m = tid + it * 256;
            int r = m >> 3, kq = (m & 7) * 4;
            const long row = row0 + r;
            float4 v = *(const float4*)(g_x + row * DMODEL + k0 + kq);
            float2 st = *(const float2*)(g_stats + row * 2);
            float4 s4 = *(const float4*)&sN[k0 + kq];
            float4 b4 = *(const float4*)&bN[k0 + kq];
            v.x = (v.x - st.x) * st.y * s4.x + b4.x;
            v.y = (v.y - st.x) * st.y * s4.y + b4.y;
            v.z = (v.z - st.x) * st.y * s4.z + b4.z;
            v.w = (v.w - st.x) * st.y * s4.w + b4.w;
            As[kq + 0][r] = v.x; As[kq + 1][r] = v.y;
            As[kq + 2][r] = v.z; As[kq + 3][r] = v.w;
        }
#pragma unroll
        for (int it = 0; it < 4; it++) {          // B tile (transposed store)
            int m = tid + it * 256;
            int cc = m >> 3, kq = (m & 7) * 4;
            float4 v = *(const float4*)(W + (long)(col0 + cc) * DMODEL + k0 + kq);
            Bs[kq + 0][cc] = v.x; Bs[kq + 1][cc] = v.y;
            Bs[kq + 2][cc] = v.z; Bs[kq + 3][cc] = v.w;
        }
        __syncthreads();
#pragma unroll
        for (int kk = 0; kk < 32; kk++) {
            // a: rows ty*8..ty*8+7 as 4 packed row-pairs
            ulonglong2 qa0 = *(const ulonglong2*)&As[kk][ty * 8];
            ulonglong2 qa1 = *(const ulonglong2*)&As[kk][ty * 8 + 4];
            unsigned long long ap0 = qa0.x, ap1 = qa0.y, ap2 = qa1.x, ap3 = qa1.y;
            // b: 8 cols, splat each
            float4 bv0 = *(const float4*)&Bs[kk][tx * 8];
            float4 bv1 = *(const float4*)&Bs[kk][tx * 8 + 4];
            unsigned long long bs[8];
            bs[0] = pk2(bv0.x, bv0.x); bs[1] = pk2(bv0.y, bv0.y);
            bs[2] = pk2(bv0.z, bv0.z); bs[3] = pk2(bv0.w, bv0.w);
            bs[4] = pk2(bv1.x, bv1.x); bs[5] = pk2(bv1.y, bv1.y);
            bs[6] = pk2(bv1.z, bv1.z); bs[7] = pk2(bv1.w, bv1.w);
#pragma unroll
            for (int j = 0; j < 8; j++) {
                acc2[0][j] = fma2(ap0, bs[j], acc2[0][j]);
                acc2[1][j] = fma2(ap1, bs[j], acc2[1][j]);
                acc2[2][j] = fma2(ap2, bs[j], acc2[2][j]);
                acc2[3][j] = fma2(ap3, bs[j], acc2[3][j]);
            }
        }
        __syncthreads();
    }
    // epilogue: rowpair rp -> rows ty*8+2rp (lo), +1 (hi)
    const int col = col0 + tx * 8;
    float4 bb0 = *(const float4*)(bias + col);
    float4 bb1 = *(const float4*)(bias + col + 4);
#pragma unroll
    for (int rp = 0; rp < 4; rp++) {
        float lo[8], hi[8];
#pragma unroll
        for (int j = 0; j < 8; j++) upk2(acc2[rp][j], lo[j], hi[j]);
        const long rlo = row0 + ty * 8 + 2 * rp;
        float4 u0, u1, v0, v1;
        u0.x = lo[0] + bb0.x; u0.y = lo[1] + bb0.y; u0.z = lo[2] + bb0.z; u0.w = lo[3] + bb0.w;
        u1.x = lo[4] + bb1.x; u1.y = lo[5] + bb1.y; u1.z = lo[6] + bb1.z; u1.w = lo[7] + bb1.w;
        v0.x = hi[0] + bb0.x; v0.y = hi[1] + bb0.y; v0.z = hi[2] + bb0.z; v0.w = hi[3] + bb0.w;
        v1.x = hi[4] + bb1.x; v1.y = hi[5] + bb1.y; v1.z = hi[6] + bb1.z; v1.w = hi[7] + bb1.w;
        *(float4*)(g_xp + rlo * G3 + col)           = u0;
        *(float4*)(g_xp + rlo * G3 + col + 4)       = u1;
        *(float4*)(g_xp + (rlo + 1) * G3 + col)     = v0;
        *(float4*)(g_xp + (rlo + 1) * G3 + col + 4) = v1;
    }
}

// =====================================================================
// Kernel 4: GRU recurrence (R11 protocol). cluster(4) per batch,
// grid (4,32), block 384. Register-resident weights, dual FFMA2 chains.
// h TRIPLE-buffered; per-step sync via st.async complete_tx.
// Reduce path: NO shfl — both kh halves STS to interleaved s_part
// (even/odd banks, conflict-free); gate threads read LDS64 pairs.
// =====================================================================
__global__ void __cluster_dims__(4, 1, 1) __launch_bounds__(384, 1)
k_gru(const float* __restrict__ whh, const float* __restrict__ bhh) {
    __shared__ __align__(16) float h_buf[3][DMODEL];
    __shared__ __align__(16) float s_part[384];   // [o*2 + kh]
    __shared__ __align__(8) unsigned long long s_bar[3];

    const int c   = blockIdx.x;          // cluster rank 0..3
    const int b   = blockIdx.y;
    const int tid = threadIdx.x;
    const int w   = tid >> 5, l = tid & 31;
    const int o   = w * 16 + (l & 15);   // 0..191: CTA-local output index
    const int kh  = l >> 4;              // k half: 0 -> k[0,128), 1 -> k[128,256)
    const int gg  = o >> 6, dd = o & 63;
    const int R   = gg * DMODEL + c * 64 + dd;   // gate row in [0,768)

    // weight slice: 128 floats = 64 f32x2 pairs in registers
    unsigned long long wreg[64];
    {
        const ulonglong2* wp = (const ulonglong2*)(whh + (long)R * DMODEL + kh * 128);
#pragma unroll
        for (int i = 0; i < 32; i++) { ulonglong2 t2 = wp[i]; wreg[2*i] = t2.x; wreg[2*i+1] = t2.y; }
    }
    const float breg = (kh == 0) ? bhh[R] : 0.0f;

    // init h buffers + mbarriers (count=1: the local expect_tx arrive)
    for (int i = tid; i < 3 * DMODEL; i += 384) ((float*)h_buf)[i] = 0.0f;
    if (tid == 0) {
#pragma unroll
        for (int mm = 0; mm < 3; mm++) {
            uint32_t ba = (uint32_t)__cvta_generic_to_shared(&s_bar[mm]);
            asm volatile("mbarrier.init.shared.b64 [%0], %1;" :: "r"(ba), "r"(1u) : "memory");
        }
    }
    __syncthreads();
    // bars + zeroed buffers visible cluster-wide before any st.async
    asm volatile("barrier.cluster.arrive.aligned;\n\tbarrier.cluster.wait.aligned;" ::: "memory");

    const uint32_t bar_loc = (uint32_t)__cvta_generic_to_shared(&s_bar[0]);
    const uint32_t h_loc   = (uint32_t)__cvta_generic_to_shared(&h_buf[0][c * 64 + (tid & 63)]);

    const float* xpb = g_xp + (long)b * SEQ * G3;
    float* xb = g_x + (long)b * SEQ * DMODEL;
    const int d = c * 64 + tid;          // gate threads: tid < 64

    float pxr = 0.f, pxz = 0.f, pxn = 0.f, pxv = 0.f;
    float hold = 0.0f;
    if (tid < 64) {
        pxr = xpb[d]; pxz = xpb[256 + d]; pxn = xpb[512 + d];
        pxv = xb[c * 64 + tid];
    }

    unsigned ph[3] = {0u, 0u, 0u};       // const-indexed after unroll -> regs

    // steps 0..998 unrolled by 3 (m compile-time); tail step 999 after.
    for (int tb = 0; tb < SEQ - 1; tb += 3) {
#pragma unroll
        for (int sub = 0; sub < 3; sub++) {
            const int t = tb + sub;
            const int m = sub;
            const int q = (sub + 1) % 3;

            // post expect_tx for next buffer early (1024 B = 4 CTA x 64 x 4B)
            if (tid == 0) {
                asm volatile("mbarrier.arrive.expect_tx.shared.b64 _, [%0], %1;"
                             :: "r"(bar_loc + q * 8), "r"(1024u) : "memory");
            }
            if (t) { mbar_wait(bar_loc + m * 8, ph[m]); ph[m] ^= 1u; }

            // ---- matvec: 64 packed FFMA2 in two independent chains ----
            unsigned long long acc2  = pk2(breg, 0.0f);
            unsigned long long acc2b = pk2(0.0f, 0.0f);
            const ulonglong2* hv = (const ulonglong2*)&h_buf[m][kh * 128];
#pragma unroll
            for (int i = 0; i < 32; i++) {
                ulonglong2 h2 = hv[i];
                acc2  = fma2(wreg[2 * i],     h2.x, acc2);
                acc2b = fma2(wreg[2 * i + 1], h2.y, acc2b);
            }
            acc2 = add2(acc2, acc2b);
            float alo, ahi;
            upk2(acc2, alo, ahi);
            s_part[o * 2 + kh] = alo + ahi;   // even/odd banks: conflict-free
            __syncthreads();

            if (tid < 64) {
                float2 p0 = *(const float2*)&s_part[tid * 2];
                float2 p1 = *(const float2*)&s_part[(64 + tid) * 2];
                float2 p2 = *(const float2*)&s_part[(128 + tid) * 2];
                const float hr = p0.x + p0.y;
                const float hz = p1.x + p1.y;
                const float hn = p2.x + p2.y;
                const float rr = fsigmoid(pxr + hr);
                const float zz = fsigmoid(pxz + hz);
                const float nn = ftanh(pxn + rr * hn);
                const float hnew = nn + zz * (hold - nn);
                hold = hnew;

                // broadcast h to buf q of all 4 CTAs; stores carry the signal
                const uint32_t dst = h_loc + q * (DMODEL * 4);
                const uint32_t bq  = bar_loc + q * 8;
#pragma unroll
                for (int r = 0; r < 4; r++) {
                    uint32_t ra, rb;
                    asm("mapa.shared::cluster.u32 %0, %1, %2;" : "=r"(ra) : "r"(dst), "r"(r));
                    asm("mapa.shared::cluster.u32 %0, %1, %2;" : "=r"(rb) : "r"(bq),  "r"(r));
                    asm volatile(
                        "st.async.shared::cluster.mbarrier::complete_tx::bytes.f32 [%0], %1, [%2];"
                        :: "r"(ra), "f"(hnew), "r"(rb) : "memory");
                }
                // residual write + next-step prefetch (latency hidden)
                xb[(long)t * DMODEL + c * 64 + tid] = pxv + hnew;
                const float* xpt = xpb + (long)(t + 1) * G3;
                pxr = xpt[d]; pxz = xpt[256 + d]; pxn = xpt[512 + d];
                pxv = xb[(long)(t + 1) * DMODEL + c * 64 + tid];
            }
        }
    }
    // ---- tail step t = SEQ-1 (m = 0): no broadcast, residual only ----
    {
        const int t = SEQ - 1;
        mbar_wait(bar_loc + 0, ph[0]);
        unsigned long long acc2  = pk2(breg, 0.0f);
        unsigned long long acc2b = pk2(0.0f, 0.0f);
        const ulonglong2* hv = (const ulonglong2*)&h_buf[0][kh * 128];
#pragma unroll
        for (int i = 0; i < 32; i++) {
            ulonglong2 h2 = hv[i];
            acc2  = fma2(wreg[2 * i],     h2.x, acc2);
            acc2b = fma2(wreg[2 * i + 1], h2.y, acc2b);
        }
        acc2 = add2(acc2, acc2b);
        float alo, ahi;
        upk2(acc2, alo, ahi);
        s_part[o * 2 + kh] = alo + ahi;
        __syncthreads();
        if (tid < 64) {
            float2 p0 = *(const float2*)&s_part[tid * 2];
            float2 p1 = *(const float2*)&s_part[(64 + tid) * 2];
            float2 p2 = *(const float2*)&s_part[(128 + tid) * 2];
            const float hr = p0.x + p0.y;
            const float hz = p1.x + p1.y;
            const float hn = p2.x + p2.y;
            const float rr = fsigmoid(pxr + hr);
            const float zz = fsigmoid(pxz + hz);
            const float nn = ftanh(pxn + rr * hn);
            const float hnew = nn + zz * (hold - nn);
            xb[(long)t * DMODEL + c * 64 + tid] = pxv + hnew;
        }
    }
    // symmetric exit (no DSMEM traffic can target an exited CTA)
    asm volatile("barrier.cluster.arrive.aligned;\n\tbarrier.cluster.wait.aligned;" ::: "memory");
}

// =====================================================================
// Kernel 5a: final LN partials. grid (25 chunks, 32 batch), block 256.
// =====================================================================
__global__ __launch_bounds__(256) void k_final_part() {
    const int ch = blockIdx.x, b = blockIdx.y;
    const int wid = threadIdx.x >> 5, lane = threadIdx.x & 31;
    const float* xb = g_x + (long)b * SEQ * DMODEL;

    float a0[4] = {0, 0, 0, 0}, a1[4] = {0, 0, 0, 0};
    for (int i = 0; i < 5; i++) {
        const int t = ch * 40 + i * 8 + wid;
        const float4* xr = (const float4*)(xb + (long)t * DMODEL);
        float4 v0 = xr[lane];
        float4 v1 = xr[lane + 32];
        float s1 = v0.x + v0.y + v0.z + v0.w + v1.x + v1.y + v1.z + v1.w;
        float s2 = v0.x * v0.x + v0.y * v0.y + v0.z * v0.z + v0.w * v0.w
                 + v1.x * v1.x + v1.y * v1.y + v1.z * v1.z + v1.w * v1.w;
#pragma unroll
        for (int o = 16; o > 0; o >>= 1) {
            s1 += __shfl_xor_sync(0xffffffffu, s1, o);
            s2 += __shfl_xor_sync(0xffffffffu, s2, o);
        }
        const float mu  = s1 * (1.0f / 256.0f);
        const float var = s2 * (1.0f / 256.0f) - mu * mu;
        const float inv = rsqrtf(var + 1e-5f);
        a0[0] += (v0.x - mu) * inv; a0[1] += (v0.y - mu) * inv;
        a0[2] += (v0.z - mu) * inv; a0[3] += (v0.w - mu) * inv;
        a1[0] += (v1.x - mu) * inv; a1[1] += (v1.y - mu) * inv;
        a1[2] += (v1.z - mu) * inv; a1[3] += (v1.w - mu) * inv;
    }
    __shared__ float red[8][DMODEL];
    float* rw = red[wid];
    *(float4*)&rw[lane * 4]       = *(float4*)a0;
    *(float4*)&rw[128 + lane * 4] = *(float4*)a1;
    __syncthreads();
    const int tid = threadIdx.x;
    if (tid < 64) {
        const int dbase = tid * 4;
        float4 s = make_float4(0, 0, 0, 0);
#pragma unroll
        for (int ww = 0; ww < 8; ww++) {
            float4 v = *(float4*)&red[ww][dbase];
            s.x += v.x; s.y += v.y; s.z += v.z; s.w += v.w;
        }
        *(float4*)&g_part[((long)b * 25 + ch) * DMODEL + dbase] = s;
    }
}

// =====================================================================
// Kernel 5b: deterministic reduce of 25 partials + scale/bias + /SEQ.
// =====================================================================
__global__ __launch_bounds__(256) void k_final_sum(const float* __restrict__ sc,
                                                   const float* __restrict__ bi) {
    const int b = blockIdx.x, tid = threadIdx.x;
    float s = 0.0f;
#pragma unroll 5
    for (int ch = 0; ch < 25; ch++) s += g_part[((long)b * 25 + ch) * DMODEL + tid];
    g_emb[b * DMODEL + tid] = s * (1.0f / (float)SEQ) * sc[tid] + bi[tid];
}

// =====================================================================
// Kernel 6: classification head. grid 32, block 128.
// =====================================================================
__global__ __launch_bounds__(128) void k_head(const float* __restrict__ w1,
                                              const float* __restrict__ b1,
                                              const float* __restrict__ w2,
                                              const float* __restrict__ b2,
                                              float* __restrict__ out) {
    const int b = blockIdx.x, tid = threadIdx.x;
    __shared__ float es[DMODEL];
    __shared__ float h1s[128];
    es[tid]       = g_emb[b * DMODEL + tid];
    es[tid + 128] = g_emb[b * DMODEL + tid + 128];
    __syncthreads();
    float a = b1[tid];
#pragma unroll 8
    for (int dmi = 0; dmi < DMODEL; dmi++) a += es[dmi] * w1[dmi * 128 + tid];
    h1s[tid] = gelu_exact(a);
    __syncthreads();
    if (tid < 8) {
        float o = b2[tid];
#pragma unroll 8
        for (int j = 0; j < 128; j++) o += h1s[j] * w2[j * 8 + tid];
        out[b * 8 + tid] = o;
    }
}

// =====================================================================
// launch
// =====================================================================
extern "C" void kernel_launch(void* const* d_in, const int* in_sizes, int n_in,
                              void* d_out, int out_size) {
    const float* waveform = (const float*)d_in[0];
    const float* conv_w   = (const float*)d_in[1];
    const float* pos_emb  = (const float*)d_in[2];
    const float* ln_scale = (const float*)d_in[3];
    const float* ln_bias  = (const float*)d_in[4];
    const float* w_ih     = (const float*)d_in[5];
    const float* w_hh     = (const float*)d_in[6];
    const float* b_ih     = (const float*)d_in[7];
    const float* b_hh     = (const float*)d_in[8];
    const float* fnorm_s  = (const float*)d_in[9];
    const float* fnorm_b  = (const float*)d_in[10];
    const float* head_w1  = (const float*)d_in[11];
    const float* head_b1  = (const float*)d_in[12];
    const float* head_w2  = (const float*)d_in[13];
    const float* head_b2  = (const float*)d_in[14];
    float* out = (float*)d_out;

    k_conv<<<500, 256>>>(waveform, conv_w, pos_emb);

    for (int lyr = 0; lyr < NLAYERS; lyr++) {
        k_ln_stats<<<4000, 256>>>();
        dim3 gg(250, 6);
        k_gemm_xp<<<gg, 256>>>(w_ih + (long)lyr * G3 * DMODEL, b_ih + lyr * G3,
                               ln_scale + lyr * DMODEL, ln_bias + lyr * DMODEL);
        dim3 gr(4, BATCH);
        k_gru<<<gr, 384>>>(w_hh + (long)lyr * G3 * DMODEL, b_hh + lyr * G3);
    }

    dim3 gf(25, BATCH);
    k_final_part<<<gf, 256>>>();
    k_final_sum<<<BATCH, 256>>>(fnorm_s, fnorm_b);
    k_head<<<BATCH, 128>>>(head_w1, head_b1, head_w2, head_b2, out);
}